// round 6
// baseline (speedup 1.0000x reference)
#include <cuda_runtime.h>
#include <math.h>

typedef unsigned long long u64;

#define TILE 16
// smem float offsets
#define SM_SX     0        // 64*400
#define SM_SPN    25600    // 2*400
#define SM_XCP    26400    // 12 slots * 400 px * 2 (pair {A,B})
#define SM_D3AP   36000    // 4 cpl * 324 * 2 (pair {h0,h1})
#define SM_DW1P   38592    // 64*27*2
#define SM_DW3AP  42048    // 64*27*2
#define SM_DW3BP  45504    // 64*9*2
#define SM_WOUTT  46656    // [cp][o] 64*64
#define SM_BDW1P  50752    // 64*2
#define SM_BDW3AP 50880
#define SM_BDW3BP 51008
#define SM_BOUT   51136    // 64
#define SM_WPN    51200    // 256
#define SM_BPN    51456    // 128
#define SM_BIN    51584    // 256
#define SM_TOTAL  51840    // 207360 bytes

// w_in transposed+paired: c_winT2[k*128 + c2] = {w_in[2c2][k], w_in[2c2+1][k]}
__constant__ u64 c_winT2[64 * 128];
__device__ u64 g_winT2[64 * 128];

__global__ void prep_winT(const float* __restrict__ w_in) {
    int i = blockIdx.x * 256 + threadIdx.x;   // 0..8191
    int k = i >> 7, c2 = i & 127;
    float lo = w_in[(2 * c2) * 64 + k];
    float hi = w_in[(2 * c2 + 1) * 64 + k];
    u64 r;
    asm("mov.b64 %0,{%1,%2};" : "=l"(r) : "f"(lo), "f"(hi));
    g_winT2[i] = r;
}

__device__ __forceinline__ u64 pk2(float lo, float hi) {
    u64 r; asm("mov.b64 %0,{%1,%2};" : "=l"(r) : "f"(lo), "f"(hi)); return r;
}
__device__ __forceinline__ void upk2(u64 v, float& lo, float& hi) {
    asm("mov.b64 {%0,%1},%2;" : "=f"(lo), "=f"(hi) : "l"(v));
}
__device__ __forceinline__ void fma2(u64& d, u64 a, u64 b) {
    asm("fma.rn.f32x2 %0,%1,%2,%0;" : "+l"(d) : "l"(a), "l"(b));
}
__device__ __forceinline__ u64 lds64(const float* p) { return *(const u64*)p; }

__device__ __forceinline__ float gelu_exact(float v) {
    return 0.5f * v * (1.0f + erff(v * 0.70710678118654752f));
}

// Phase A: fused both halves in one k-loop. NPAIRS = # of A-side xi pairs {0,2,6}.
template<int NPAIRS, bool TWO>
__device__ __forceinline__ void phaseA(float* sm, int g, int q0, int q1, bool has2,
                                       float m0, float m1,
                                       float pnA0, float pnB0, float pnA1, float pnB1)
{
    const int bBase = 64 + 12 * g;                               // half1 xi base (even)
    const int aBase = (NPAIRS == 2) ? (12 * g - 120) : (12 * g - 128);
    u64 aB0[6], aB1[6];
    u64 aA0[NPAIRS > 0 ? NPAIRS : 1], aA1[NPAIRS > 0 ? NPAIRS : 1];
#pragma unroll
    for (int j = 0; j < 6; ++j) {
        u64 bp = lds64(sm + SM_BIN + bBase + 2 * j);
        aB0[j] = bp; if (TWO) aB1[j] = bp;
    }
#pragma unroll
    for (int j = 0; j < NPAIRS; ++j) {
        u64 bp = lds64(sm + SM_BIN + aBase + 2 * j);
        aA0[j] = bp; if (TWO) aA1[j] = bp;
    }
    const int bIdx = 32 + 6 * g;
    const int aIdx = aBase >> 1;
#pragma unroll 4
    for (int k = 0; k < 64; ++k) {
        float s0 = sm[SM_SX + k * 400 + q0];
        u64 s0p = pk2(s0, s0);
        u64 s1p = 0;
        if (TWO) { float s1 = sm[SM_SX + k * 400 + q1]; s1p = pk2(s1, s1); }
        const u64* wB = c_winT2 + k * 128 + bIdx;
#pragma unroll
        for (int j = 0; j < 6; ++j) {
            u64 w = wB[j];
            fma2(aB0[j], w, s0p);
            if (TWO) fma2(aB1[j], w, s1p);
        }
        if (NPAIRS > 0) {
            const u64* wA = c_winT2 + k * 128 + aIdx;
#pragma unroll
            for (int j = 0; j < NPAIRS; ++j) {
                u64 w = wA[j];
                fma2(aA0[j], w, s0p);
                if (TWO) fma2(aA1[j], w, s1p);
            }
        }
    }
    float B0[12], B1v[12], A0[12], A1v[12];
#pragma unroll
    for (int j = 0; j < 6; ++j) { upk2(aB0[j], B0[2 * j], B0[2 * j + 1]); }
    if (TWO) {
#pragma unroll
        for (int j = 0; j < 6; ++j) { upk2(aB1[j], B1v[2 * j], B1v[2 * j + 1]); }
    }
    if (NPAIRS == 6) {
#pragma unroll
        for (int j = 0; j < 6; ++j) {
            upk2(aA0[j], A0[2 * j], A0[2 * j + 1]);
            if (TWO) upk2(aA1[j], A1v[2 * j], A1v[2 * j + 1]);
        }
    } else if (NPAIRS == 2) {
        upk2(aA0[0], A0[8], A0[9]);  upk2(aA0[1], A0[10], A0[11]);
        if (TWO) { upk2(aA1[0], A1v[8], A1v[9]); upk2(aA1[1], A1v[10], A1v[11]); }
    }
#pragma unroll
    for (int s = 0; s < 12; ++s) {
        const bool isPN = (NPAIRS == 0) || (NPAIRS == 2 && s < 8);
        if (isPN) {
            int c = 12 * g + s;
            float w0 = sm[SM_WPN + 2 * c], w1 = sm[SM_WPN + 2 * c + 1], bb = sm[SM_BPN + c];
            A0[s] = fmaf(w0, pnA0, fmaf(w1, pnB0, bb));
            if (TWO) A1v[s] = fmaf(w0, pnA1, fmaf(w1, pnB1, bb));
        }
        float2 v0; v0.x = A0[s] * m0; v0.y = B0[s] * m0;
        *(float2*)&sm[SM_XCP + (s * 400 + q0) * 2] = v0;
        if (TWO && has2) {
            float2 v1; v1.x = A1v[s] * m1; v1.y = B1v[s] * m1;
            *(float2*)&sm[SM_XCP + (s * 400 + q1) * 2] = v1;
        }
    }
}

__global__ void __launch_bounds__(256, 1)
ffn_fused_kernel(const float* __restrict__ x,
                 const float* __restrict__ pneff,
                 const float* __restrict__ w_pn,  const float* __restrict__ b_pn,
                 const float* __restrict__ w_dw1, const float* __restrict__ b_dw1,
                 const float* __restrict__ w_dw3a,const float* __restrict__ b_dw3a,
                 const float* __restrict__ w_dw3b,const float* __restrict__ b_dw3b,
                 const float* __restrict__ w_out, const float* __restrict__ b_out,
                 const float* __restrict__ b_in,
                 float* __restrict__ out)
{
    extern __shared__ float sm[];
    const int tid = threadIdx.x;
    const int bx0 = blockIdx.x * TILE;
    const int by0 = blockIdx.y * TILE;
    const int b   = blockIdx.z;

    // ---- stage paired weights/biases (once per block) ----
    for (int v = tid; v < 1728; v += 256) {
        int cp = v / 27, t = v - cp * 27;
        sm[SM_DW1P + 2 * v]      = w_dw1[cp * 27 + t];
        sm[SM_DW1P + 2 * v + 1]  = w_dw1[(cp + 64) * 27 + t];
        sm[SM_DW3AP + 2 * v]     = w_dw3a[cp * 27 + t];
        sm[SM_DW3AP + 2 * v + 1] = w_dw3a[(cp + 64) * 27 + t];
    }
    for (int v = tid; v < 576; v += 256) {
        int cp = v / 9, t = v - cp * 9;
        sm[SM_DW3BP + 2 * v]     = w_dw3b[cp * 9 + t];
        sm[SM_DW3BP + 2 * v + 1] = w_dw3b[(cp + 64) * 9 + t];
    }
    for (int v = tid; v < 4096; v += 256) {
        int o = v >> 6, cp = v & 63;
        sm[SM_WOUTT + cp * 64 + o] = w_out[v];
    }
    if (tid < 64) {
        sm[SM_BDW1P + 2 * tid]      = b_dw1[tid];
        sm[SM_BDW1P + 2 * tid + 1]  = b_dw1[tid + 64];
        sm[SM_BDW3AP + 2 * tid]     = b_dw3a[tid];
        sm[SM_BDW3AP + 2 * tid + 1] = b_dw3a[tid + 64];
        sm[SM_BDW3BP + 2 * tid]     = b_dw3b[tid];
        sm[SM_BDW3BP + 2 * tid + 1] = b_dw3b[tid + 64];
        sm[SM_BOUT + tid] = b_out[tid];
    }
    sm[SM_WPN + tid] = w_pn[tid];
    sm[SM_BIN + tid] = b_in[tid];
    if (tid < 128) sm[SM_BPN + tid] = b_pn[tid];

    // ---- stage x tile (20x20 halo, 64 ch) + pn tile ----
    {
        const float* xb = x + (size_t)b * 64 * 65536;
        for (int c = 0; c < 64; ++c) {
            const float* xcp = xb + (size_t)c * 65536;
            for (int p = tid; p < 400; p += 256) {
                int ry = p / 20, rx = p - ry * 20;
                int gy = by0 + ry - 2, gx = bx0 + rx - 2;
                float vv = 0.0f;
                if ((unsigned)gy < 256u && (unsigned)gx < 256u) vv = xcp[gy * 256 + gx];
                sm[SM_SX + c * 400 + p] = vv;
            }
        }
        const float* pnb = pneff + (size_t)b * 2 * 65536;
        for (int c = 0; c < 2; ++c) {
            const float* pcp = pnb + (size_t)c * 65536;
            for (int p = tid; p < 400; p += 256) {
                int ry = p / 20, rx = p - ry * 20;
                int gy = by0 + ry - 2, gx = bx0 + rx - 2;
                float vv = 0.0f;
                if ((unsigned)gy < 256u && (unsigned)gx < 256u) vv = pcp[gy * 256 + gx];
                sm[SM_SPN + c * 400 + p] = vv;
            }
        }
    }
    __syncthreads();

    const int q0 = tid;
    const bool has2 = (tid < 144);
    const bool two  = (tid < 160);          // warps 0-4 run dual-pixel path
    const int q1 = has2 ? (256 + tid) : q0;
    float m0, m1;
    {
        int ry = q0 / 20, rx = q0 - ry * 20;
        m0 = ((unsigned)(by0 + ry - 2) < 256u && (unsigned)(bx0 + rx - 2) < 256u) ? 1.f : 0.f;
        int ry1 = q1 / 20, rx1 = q1 - ry1 * 20;
        m1 = (has2 && (unsigned)(by0 + ry1 - 2) < 256u && (unsigned)(bx0 + rx1 - 2) < 256u) ? 1.f : 0.f;
    }
    const float pnA0 = sm[SM_SPN + q0], pnB0 = sm[SM_SPN + 400 + q0];
    const float pnA1 = sm[SM_SPN + q1], pnB1 = sm[SM_SPN + 400 + q1];

    const int ty = tid >> 4;
    const int tx = tid & 15;
    const int warp = tid >> 5;
    const int lane = tid & 31;

    u64 acc2[16], acc3[16];
#pragma unroll
    for (int m = 0; m < 16; ++m) { acc2[m] = 0ULL; acc3[m] = 0ULL; }

    for (int g = 0; g < 16; ++g) {
        // ---- Phase A ----
        if (two) {
            if (g < 10)       phaseA<0, true>(sm, g, q0, q1, has2, m0, m1, pnA0, pnB0, pnA1, pnB1);
            else if (g == 10) phaseA<2, true>(sm, g, q0, q1, has2, m0, m1, pnA0, pnB0, pnA1, pnB1);
            else              phaseA<6, true>(sm, g, q0, q1, has2, m0, m1, pnA0, pnB0, pnA1, pnB1);
        } else {
            if (g < 10)       phaseA<0, false>(sm, g, q0, q1, has2, m0, m1, pnA0, pnB0, pnA1, pnB1);
            else if (g == 10) phaseA<2, false>(sm, g, q0, q1, has2, m0, m1, pnA0, pnB0, pnA1, pnB1);
            else              phaseA<6, false>(sm, g, q0, q1, has2, m0, m1, pnA0, pnB0, pnA1, pnB1);
        }
        __syncthreads();   // XC ready

        // ---- B1 (all threads, 1 px, 4 cpls, packed pairs) ----
#pragma unroll
        for (int cpl = 0; cpl < 4; ++cpl) {
            const int cp = 4 * g + cpl;
            u64 d1 = lds64(sm + SM_BDW1P + 2 * cp);
            const float* wp = sm + SM_DW1P + cp * 54;
            const float* xb = sm + SM_XCP + (3 * cpl * 400) * 2;
#pragma unroll
            for (int j = 0; j < 3; ++j)
#pragma unroll
                for (int ky = 0; ky < 3; ++ky)
#pragma unroll
                    for (int kx = 0; kx < 3; ++kx) {
                        int t = j * 9 + ky * 3 + kx;
                        u64 w  = lds64(wp + 2 * t);
                        u64 xv = lds64(xb + (j * 400 + (ty + 1 + ky) * 20 + (tx + 1 + kx)) * 2);
                        fma2(d1, w, xv);
                    }
            float d1a, d1b; upk2(d1, d1a, d1b);
            float g1 = gelu_exact(d1a) * d1b;
            u64 g1p = pk2(g1, g1);
            const ulonglong2* wo = (const ulonglong2*)(sm + SM_WOUTT + cp * 64);
#pragma unroll
            for (int m = 0; m < 8; ++m) {
                ulonglong2 w2 = wo[m];
                fma2(acc2[2 * m], w2.x, g1p);
                fma2(acc2[2 * m + 1], w2.y, g1p);
            }
        }

        // ---- B2 (warp-split: cpl = warp>>1, px-half = warp&1; packed {h0,h1}) ----
        {
            const int cpl = warp >> 1, h2 = warp & 1;
            const int cp = 4 * g + cpl;
            u64 bias = lds64(sm + SM_BDW3AP + 2 * cp);
            const float* wp = sm + SM_DW3AP + cp * 54;
            const float* xb = sm + SM_XCP + (3 * cpl * 400) * 2;
            float* dst = sm + SM_D3AP + (cpl * 324) * 2;
            for (int i = 162 * h2 + lane; i < 162 * h2 + 162; i += 32) {
                int qy = i / 18, qx = i - qy * 18;
                int gy = by0 + qy - 1, gx = bx0 + qx - 1;
                u64 d = bias;
#pragma unroll
                for (int j = 0; j < 3; ++j)
#pragma unroll
                    for (int ky = 0; ky < 3; ++ky)
#pragma unroll
                        for (int kx = 0; kx < 3; ++kx) {
                            u64 w  = lds64(wp + 2 * (j * 9 + ky * 3 + kx));
                            u64 xv = lds64(xb + (j * 400 + (qy + ky) * 20 + qx + kx) * 2);
                            fma2(d, w, xv);
                        }
                float da, db; upk2(d, da, db);
                bool ok = ((unsigned)gy < 256u) && ((unsigned)gx < 256u);
                float2 v; v.x = ok ? da : 0.f; v.y = ok ? db : 0.f;
                *(float2*)&dst[2 * i] = v;
            }
        }
        __syncthreads();   // D3A ready

        // ---- B3 (all threads, 1 px, packed {dA,dB}) + proj o32..63 ----
#pragma unroll
        for (int cpl = 0; cpl < 4; ++cpl) {
            const int cp = 4 * g + cpl;
            u64 d = lds64(sm + SM_BDW3BP + 2 * cp);
            const float* wp = sm + SM_DW3BP + cp * 18;
            const float* db3 = sm + SM_D3AP + cpl * 648;
#pragma unroll
            for (int ky = 0; ky < 3; ++ky)
#pragma unroll
                for (int kx = 0; kx < 3; ++kx) {
                    u64 w  = lds64(wp + 2 * (ky * 3 + kx));
                    u64 xv = lds64(db3 + ((ty + ky) * 18 + tx + kx) * 2);
                    fma2(d, w, xv);
                }
            float da, dbv; upk2(d, da, dbv);
            float g2 = gelu_exact(da) * dbv;
            u64 g2p = pk2(g2, g2);
            const ulonglong2* wo = (const ulonglong2*)(sm + SM_WOUTT + cp * 64 + 32);
#pragma unroll
            for (int m = 0; m < 8; ++m) {
                ulonglong2 w2 = wo[m];
                fma2(acc3[2 * m], w2.x, g2p);
                fma2(acc3[2 * m + 1], w2.y, g2p);
            }
        }
        __syncthreads();   // protect XCP/D3AP for next group
    }

    // ---- write output ----
    float* ob = out + (size_t)b * 64 * 65536 + (size_t)(by0 + ty) * 256 + (bx0 + tx);
#pragma unroll
    for (int m = 0; m < 16; ++m) {
        float o0, o1; upk2(acc2[m], o0, o1);
        ob[(size_t)(2 * m) * 65536]     = o0 + sm[SM_BOUT + 2 * m];
        ob[(size_t)(2 * m + 1) * 65536] = o1 + sm[SM_BOUT + 2 * m + 1];
    }
#pragma unroll
    for (int m = 0; m < 16; ++m) {
        float o0, o1; upk2(acc3[m], o0, o1);
        ob[(size_t)(32 + 2 * m) * 65536] = o0 + sm[SM_BOUT + 32 + 2 * m];
        ob[(size_t)(33 + 2 * m) * 65536] = o1 + sm[SM_BOUT + 33 + 2 * m];
    }
}

extern "C" void kernel_launch(void* const* d_in, const int* in_sizes, int n_in,
                              void* d_out, int out_size)
{
    (void)in_sizes; (void)n_in; (void)out_size;
    const float* x      = (const float*)d_in[0];
    const float* pneff  = (const float*)d_in[1];
    const float* w_in   = (const float*)d_in[2];
    float* out = (float*)d_out;

    prep_winT<<<32, 256>>>(w_in);
    void* p_winT = nullptr;
    cudaGetSymbolAddress(&p_winT, g_winT2);
    cudaMemcpyToSymbolAsync(c_winT2, p_winT, 64 * 128 * sizeof(u64), 0,
                            cudaMemcpyDeviceToDevice, 0);

    const size_t smem_bytes = SM_TOTAL * sizeof(float);
    cudaFuncSetAttribute(ffn_fused_kernel,
                         cudaFuncAttributeMaxDynamicSharedMemorySize,
                         (int)smem_bytes);
    dim3 grid(16, 16, 4);
    ffn_fused_kernel<<<grid, 256, smem_bytes>>>(
        x, pneff,
        (const float*)d_in[4],  (const float*)d_in[5],
        (const float*)d_in[6],  (const float*)d_in[7],
        (const float*)d_in[8],  (const float*)d_in[9],
        (const float*)d_in[10], (const float*)d_in[11],
        (const float*)d_in[12], (const float*)d_in[13],
        (const float*)d_in[3],
        out);
}